// round 1
// baseline (speedup 1.0000x reference)
#include <cuda_runtime.h>
#include <cuda_bf16.h>
#include <math.h>

// ---------------- problem constants ----------------
#define B_   2
#define S_   4096
#define D_   512
#define BPL_ 4
#define H_   16
#define DQK_ 64
#define DLAT_ 1024
#define LQ_  (S_ / BPL_)          // 1024
#define EPS_ 1.1920929e-07f

// ---------------- scratch (device globals; no allocation allowed) ----------------
__device__ float g_norm  [B_ * S_ * D_];          // 16MB  normalized (B,S,D)
__device__ float g_qproj [B_ * LQ_ * H_ * DQK_];  // 8MB   (B*LQ, 1024)
__device__ float g_kvproj[B_ * S_ * 2 * H_ * DQK_]; // 64MB (B*S, 2048)
__device__ float g_q     [B_ * H_ * LQ_ * DQK_];  // 8MB   (B,H,LQ,64)
__device__ float g_k     [B_ * H_ * S_  * DQK_];  // 32MB  (B,H,S,64)
__device__ float g_v     [B_ * H_ * S_  * DQK_];  // 32MB  (B,H,S,64)
__device__ float g_attn  [B_ * LQ_ * H_ * DQK_];  // 8MB   (B*LQ, 1024)

// ---------------- RMSNorm: one block (128 thr) per row of 512 ----------------
__global__ __launch_bounds__(128) void rmsnorm_kernel(
    const float* __restrict__ x, const float* __restrict__ w, float* __restrict__ out)
{
    int row = blockIdx.x;
    const float4* xr = (const float4*)(x + (size_t)row * D_);
    float4* outr = (float4*)(out + (size_t)row * D_);
    const float4* wr = (const float4*)w;
    int tid = threadIdx.x;

    float4 v = xr[tid];
    float s = v.x * v.x + v.y * v.y + v.z * v.z + v.w * v.w;
    // warp reduce
    #pragma unroll
    for (int o = 16; o > 0; o >>= 1) s += __shfl_xor_sync(0xffffffffu, s, o);
    __shared__ float red[4];
    int warp = tid >> 5, lane = tid & 31;
    if (lane == 0) red[warp] = s;
    __syncthreads();
    float total = red[0] + red[1] + red[2] + red[3];
    float inv = rsqrtf(total / (float)D_ + EPS_);
    float4 wv = wr[tid];
    float4 o4;
    o4.x = v.x * inv * wv.x;
    o4.y = v.y * inv * wv.y;
    o4.z = v.z * inv * wv.z;
    o4.w = v.w * inv * wv.w;
    outr[tid] = o4;
}

// ---------------- SGEMM 128x128x8, 8x8 per thread, 256 threads ----------------
// C[M,N] = A[M,K] @ Bm[K,N] (+ bias[col]) (+ C if accum)
// Requires M%128==0, N%128==0, K%8==0 (true for all calls here).
#define GBM 128
#define GBN 128
#define GBK 8
#define GTM 8
#define GTN 8
__global__ __launch_bounds__(256) void sgemm_kernel(
    int M, int N, int K,
    const float* __restrict__ A, const float* __restrict__ Bm,
    const float* __restrict__ bias, float* __restrict__ C, int accum)
{
    __shared__ float As[GBK][GBM];
    __shared__ float Bs[GBK][GBN];

    const int cRow = blockIdx.y;
    const int cCol = blockIdx.x;
    const int tid = threadIdx.x;

    const int tRow = tid / 16;   // 0..15
    const int tCol = tid % 16;   // 0..15

    const int aRow = tid / 2;          // 0..127
    const int aCol = (tid % 2) * 4;    // 0 or 4
    const int bRow = tid / 32;         // 0..7
    const int bCol = (tid % 32) * 4;   // 0..124

    const float* Ablk = A + (size_t)cRow * GBM * K;
    const float* Bblk = Bm + cCol * GBN;

    float acc[GTM][GTN];
    #pragma unroll
    for (int i = 0; i < GTM; i++)
        #pragma unroll
        for (int j = 0; j < GTN; j++) acc[i][j] = 0.0f;

    float regM[GTM], regN[GTN];

    for (int k0 = 0; k0 < K; k0 += GBK) {
        float4 a = *(const float4*)(Ablk + (size_t)aRow * K + k0 + aCol);
        As[aCol + 0][aRow] = a.x;
        As[aCol + 1][aRow] = a.y;
        As[aCol + 2][aRow] = a.z;
        As[aCol + 3][aRow] = a.w;
        float4 b = *(const float4*)(Bblk + (size_t)(k0 + bRow) * N + bCol);
        *(float4*)&Bs[bRow][bCol] = b;
        __syncthreads();

        #pragma unroll
        for (int k = 0; k < GBK; k++) {
            #pragma unroll
            for (int i = 0; i < GTM; i++) regM[i] = As[k][tRow * GTM + i];
            #pragma unroll
            for (int j = 0; j < GTN; j++) regN[j] = Bs[k][tCol * GTN + j];
            #pragma unroll
            for (int i = 0; i < GTM; i++)
                #pragma unroll
                for (int j = 0; j < GTN; j++)
                    acc[i][j] += regM[i] * regN[j];
        }
        __syncthreads();
    }

    // epilogue
    const int colBase = cCol * GBN + tCol * GTN;
    #pragma unroll
    for (int i = 0; i < GTM; i++) {
        int row = cRow * GBM + tRow * GTM + i;
        float* crow = C + (size_t)row * N + colBase;
        #pragma unroll
        for (int j = 0; j < GTN; j += 4) {
            float4 r = make_float4(acc[i][j], acc[i][j + 1], acc[i][j + 2], acc[i][j + 3]);
            if (bias) {
                float4 bb = *(const float4*)&bias[colBase + j];
                r.x += bb.x; r.y += bb.y; r.z += bb.z; r.w += bb.w;
            }
            if (accum) {
                float4 c = *(const float4*)&crow[j];
                r.x += c.x; r.y += c.y; r.z += c.z; r.w += c.w;
            }
            *(float4*)&crow[j] = r;
        }
    }
}

// ---------------- RoPE helpers ----------------
__device__ __forceinline__ float inv_freq_f(int d)
{
    // match jnp fp32 pow: compute in double, round once to fp32
    return (float)pow(10000.0, -(double)d / 32.0);
}

// q: (B,LQ,H,64) proj -> rope -> (B,H,LQ,64); pos = qi*4
__global__ __launch_bounds__(256) void rope_q_kernel(
    const float* __restrict__ qp, float* __restrict__ q)
{
    int idx = blockIdx.x * blockDim.x + threadIdx.x;  // B*LQ*H*32 = 1,048,576
    int d  = idx & 31;
    int h  = (idx >> 5) & 15;
    int qi = (idx >> 9) & 1023;
    int b  = idx >> 19;
    const float* src = qp + ((size_t)(b * LQ_ + qi) * (H_ * DQK_)) + h * DQK_;
    float x1 = src[d], x2 = src[d + 32];
    float pos = (float)(qi * BPL_);
    float ang = pos * inv_freq_f(d);
    float c = cosf(ang), s = sinf(ang);
    float* dst = q + (((size_t)(b * H_ + h) * LQ_) + qi) * DQK_;
    dst[d]      = x1 * c - x2 * s;
    dst[d + 32] = x1 * s + x2 * c;
}

// k: kvproj cols [0,1024) -> rope -> (B,H,S,64); pos = s
__global__ __launch_bounds__(256) void rope_k_kernel(
    const float* __restrict__ kvp, float* __restrict__ k)
{
    int idx = blockIdx.x * blockDim.x + threadIdx.x;  // B*S*H*32 = 4,194,304
    int d  = idx & 31;
    int h  = (idx >> 5) & 15;
    int s  = (idx >> 9) & 4095;
    int b  = idx >> 21;
    const float* src = kvp + ((size_t)(b * S_ + s) * (2 * H_ * DQK_)) + h * DQK_;
    float x1 = src[d], x2 = src[d + 32];
    float pos = (float)s;
    float ang = pos * inv_freq_f(d);
    float c = cosf(ang), sn = sinf(ang);
    float* dst = k + (((size_t)(b * H_ + h) * S_) + s) * DQK_;
    dst[d]      = x1 * c - x2 * sn;
    dst[d + 32] = x1 * sn + x2 * c;
}

// v: kvproj cols [1024,2048) -> (B,H,S,64), float4 copy
__global__ __launch_bounds__(256) void vtrans_kernel(
    const float* __restrict__ kvp, float* __restrict__ v)
{
    int idx = blockIdx.x * blockDim.x + threadIdx.x;  // B*S*H*16 = 2,097,152 float4s
    int d4 = idx & 15;
    int h  = (idx >> 4) & 15;
    int s  = (idx >> 8) & 4095;
    int b  = idx >> 20;
    const float4* src = (const float4*)(kvp + ((size_t)(b * S_ + s) * (2 * H_ * DQK_))
                                        + H_ * DQK_ + h * DQK_);
    float4* dst = (float4*)(v + (((size_t)(b * H_ + h) * S_) + s) * DQK_);
    dst[d4] = src[d4];
}

// ---------------- flash attention: thread-per-query, 128 q / CTA ----------------
// q,k,v: (B,H,*,64); out: attn_concat (B*LQ, H*64)
#define FKT 32   // key tile
__global__ __launch_bounds__(128) void flash_kernel(
    const float* __restrict__ q, const float* __restrict__ k,
    const float* __restrict__ v, float* __restrict__ out)
{
    const int bh = blockIdx.y;                 // 0..31 (b*16+h)
    const int qi = blockIdx.x * 128 + threadIdx.x;

    const float* qrow = q + ((size_t)bh * LQ_ + qi) * DQK_;
    float qreg[DQK_];
    #pragma unroll
    for (int i = 0; i < 16; i++) {
        float4 t = ((const float4*)qrow)[i];
        qreg[4 * i] = t.x; qreg[4 * i + 1] = t.y; qreg[4 * i + 2] = t.z; qreg[4 * i + 3] = t.w;
    }

    __shared__ float ksm[FKT * DQK_];
    __shared__ float vsm[FKT * DQK_];
    const float* kbase = k + (size_t)bh * S_ * DQK_;
    const float* vbase = v + (size_t)bh * S_ * DQK_;

    float m = -1e30f, l = 0.0f;
    float acc[DQK_];
    #pragma unroll
    for (int d = 0; d < DQK_; d++) acc[d] = 0.0f;
    const float scale = 0.125f;  // 1/sqrt(64)

    for (int j0 = 0; j0 < S_; j0 += FKT) {
        __syncthreads();
        // load 32x64 = 2048 floats each buffer: 512 float4s / 128 threads = 4 each
        const float4* ksrc = (const float4*)(kbase + (size_t)j0 * DQK_);
        const float4* vsrc = (const float4*)(vbase + (size_t)j0 * DQK_);
        #pragma unroll
        for (int t = 0; t < 4; t++) {
            int i = threadIdx.x + t * 128;
            ((float4*)ksm)[i] = ksrc[i];
            ((float4*)vsm)[i] = vsrc[i];
        }
        __syncthreads();

        float sreg[FKT];
        #pragma unroll
        for (int j = 0; j < FKT; j++) {
            const float4* kr = (const float4*)&ksm[j * DQK_];
            float s = 0.0f;
            #pragma unroll
            for (int d4 = 0; d4 < 16; d4++) {
                float4 kk = kr[d4];
                s += qreg[4 * d4]     * kk.x;
                s += qreg[4 * d4 + 1] * kk.y;
                s += qreg[4 * d4 + 2] * kk.z;
                s += qreg[4 * d4 + 3] * kk.w;
            }
            sreg[j] = s * scale;
        }

        float tmax = sreg[0];
        #pragma unroll
        for (int j = 1; j < FKT; j++) tmax = fmaxf(tmax, sreg[j]);
        float mnew = fmaxf(m, tmax);
        float corr = __expf(m - mnew);
        l *= corr;
        #pragma unroll
        for (int d = 0; d < DQK_; d++) acc[d] *= corr;
        m = mnew;

        #pragma unroll
        for (int j = 0; j < FKT; j++) {
            float p = __expf(sreg[j] - m);
            l += p;
            const float4* vr = (const float4*)&vsm[j * DQK_];
            #pragma unroll
            for (int d4 = 0; d4 < 16; d4++) {
                float4 vv = vr[d4];
                acc[4 * d4]     += p * vv.x;
                acc[4 * d4 + 1] += p * vv.y;
                acc[4 * d4 + 2] += p * vv.z;
                acc[4 * d4 + 3] += p * vv.w;
            }
        }
    }

    float inv = 1.0f / l;
    int b = bh >> 4, h = bh & 15;
    float* o = out + ((size_t)(b * LQ_ + qi) * (H_ * DQK_)) + h * DQK_;
    #pragma unroll
    for (int d4 = 0; d4 < 16; d4++) {
        float4 r = make_float4(acc[4 * d4] * inv, acc[4 * d4 + 1] * inv,
                               acc[4 * d4 + 2] * inv, acc[4 * d4 + 3] * inv);
        ((float4*)o)[d4] = r;
    }
}

// ---------------- launch ----------------
extern "C" void kernel_launch(void* const* d_in, const int* in_sizes, int n_in,
                              void* d_out, int out_size)
{
    (void)in_sizes; (void)n_in; (void)out_size;
    const float* x      = (const float*)d_in[0];
    const float* norm_w = (const float*)d_in[1];
    const float* wq_w   = (const float*)d_in[2];
    const float* wq_b   = (const float*)d_in[3];
    const float* wkv_w  = (const float*)d_in[4];
    const float* wkv_b  = (const float*)d_in[5];
    const float* wout_w = (const float*)d_in[6];
    const float* wout_b = (const float*)d_in[7];
    const float* wbyp_w = (const float*)d_in[8];
    float* out = (float*)d_out;

    float *p_norm, *p_qproj, *p_kvproj, *p_q, *p_k, *p_v, *p_attn;
    cudaGetSymbolAddress((void**)&p_norm,   g_norm);
    cudaGetSymbolAddress((void**)&p_qproj,  g_qproj);
    cudaGetSymbolAddress((void**)&p_kvproj, g_kvproj);
    cudaGetSymbolAddress((void**)&p_q,      g_q);
    cudaGetSymbolAddress((void**)&p_k,      g_k);
    cudaGetSymbolAddress((void**)&p_v,      g_v);
    cudaGetSymbolAddress((void**)&p_attn,   g_attn);

    // 1. RMSNorm: 8192 rows
    rmsnorm_kernel<<<B_ * S_, 128>>>(x, norm_w, p_norm);

    // 2. Q projection: (2048 x 2048) @ (2048 x 1024) + bias
    sgemm_kernel<<<dim3((H_ * DQK_) / GBN, (B_ * LQ_) / GBM), 256>>>(
        B_ * LQ_, H_ * DQK_, BPL_ * D_, p_norm, wq_w, wq_b, p_qproj, 0);

    // 3. KV projection: (8192 x 512) @ (512 x 2048) + bias
    sgemm_kernel<<<dim3((2 * H_ * DQK_) / GBN, (B_ * S_) / GBM), 256>>>(
        B_ * S_, 2 * H_ * DQK_, D_, p_norm, wkv_w, wkv_b, p_kvproj, 0);

    // 4. RoPE + transposes
    rope_q_kernel<<<(B_ * LQ_ * H_ * 32) / 256, 256>>>(p_qproj, p_q);
    rope_k_kernel<<<(B_ * S_ * H_ * 32) / 256, 256>>>(p_kvproj, p_k);
    vtrans_kernel<<<(B_ * S_ * H_ * 16) / 256, 256>>>(p_kvproj, p_v);

    // 5. Flash attention -> attn_concat (2048 x 1024)
    flash_kernel<<<dim3(LQ_ / 128, B_ * H_), 128>>>(p_q, p_k, p_v, p_attn);

    // 6. Bypass: out = x_merged (2048 x 2048) @ wbyp (2048 x 1024)
    sgemm_kernel<<<dim3(DLAT_ / GBN, (B_ * LQ_) / GBM), 256>>>(
        B_ * LQ_, DLAT_, BPL_ * D_, x, wbyp_w, nullptr, out, 0);

    // 7. Out projection (accumulate): out += attn_concat @ wout + wout_b
    sgemm_kernel<<<dim3(DLAT_ / GBN, (B_ * LQ_) / GBM), 256>>>(
        B_ * LQ_, DLAT_, H_ * DQK_, p_attn, wout_w, wout_b, out, 1);
}

// round 4
// speedup vs baseline: 1.4724x; 1.4724x over previous
#include <cuda_runtime.h>
#include <cuda_bf16.h>
#include <math.h>
#include <stdint.h>

// ---------------- problem constants ----------------
#define B_   2
#define S_   4096
#define D_   512
#define BPL_ 4
#define H_   16
#define DQK_ 64
#define DLAT_ 1024
#define LQ_  (S_ / BPL_)          // 1024
#define EPS_ 1.1920929e-07f

// ---------------- scratch (device globals; no allocation allowed) ----------------
__device__ float g_qproj [B_ * LQ_ * H_ * DQK_];
__device__ float g_kvproj[B_ * S_ * 2 * H_ * DQK_];
__device__ float g_q     [B_ * H_ * LQ_ * DQK_];
__device__ float g_k     [B_ * H_ * S_  * DQK_];
__device__ float g_v     [B_ * H_ * S_  * DQK_];
__device__ float g_attn  [B_ * LQ_ * H_ * DQK_];

// bf16 hi/lo split operands
__device__ __nv_bfloat16 g_normh[B_ * S_ * D_], g_norml[B_ * S_ * D_];
__device__ __nv_bfloat16 g_xh   [B_ * S_ * D_], g_xl   [B_ * S_ * D_];
__device__ __nv_bfloat16 g_wqh  [BPL_ * D_ * H_ * DQK_],  g_wql  [BPL_ * D_ * H_ * DQK_];
__device__ __nv_bfloat16 g_wkvh [D_ * 2 * H_ * DQK_],     g_wkvl [D_ * 2 * H_ * DQK_];
__device__ __nv_bfloat16 g_wouth[H_ * DQK_ * DLAT_],      g_woutl[H_ * DQK_ * DLAT_];
__device__ __nv_bfloat16 g_wbyph[BPL_ * D_ * DLAT_],      g_wbypl[BPL_ * D_ * DLAT_];
__device__ __nv_bfloat16 g_attnh[B_ * LQ_ * H_ * DQK_],   g_attnl[B_ * LQ_ * H_ * DQK_];

// ---------------- helpers ----------------
__device__ __forceinline__ uint32_t smem_to_u32(const void* p) {
    uint32_t a;
    asm("{ .reg .u64 t; cvta.to.shared.u64 t, %1; cvt.u32.u64 %0, t; }" : "=r"(a) : "l"(p));
    return a;
}

#define CP_ASYNC16(dst, src) \
    asm volatile("cp.async.cg.shared.global [%0], [%1], 16;" :: "r"(dst), "l"(src))
#define CP_COMMIT()  asm volatile("cp.async.commit_group;" ::: "memory")
#define CP_WAIT1()   asm volatile("cp.async.wait_group 1;" ::: "memory")
#define CP_WAIT0()   asm volatile("cp.async.wait_group 0;" ::: "memory")

__device__ __forceinline__ void ldmA(uint32_t* r, uint32_t addr) {
    asm volatile("ldmatrix.sync.aligned.m8n8.x4.shared.b16 {%0,%1,%2,%3}, [%4];"
                 : "=r"(r[0]), "=r"(r[1]), "=r"(r[2]), "=r"(r[3]) : "r"(addr));
}
__device__ __forceinline__ void ldmBT(uint32_t* r, uint32_t addr) {
    asm volatile("ldmatrix.sync.aligned.m8n8.x4.trans.shared.b16 {%0,%1,%2,%3}, [%4];"
                 : "=r"(r[0]), "=r"(r[1]), "=r"(r[2]), "=r"(r[3]) : "r"(addr));
}
__device__ __forceinline__ void mma16816(float* d, const uint32_t* a, const uint32_t* b) {
    asm volatile(
        "mma.sync.aligned.m16n8k16.row.col.f32.bf16.bf16.f32 "
        "{%0,%1,%2,%3}, {%4,%5,%6,%7}, {%8,%9}, {%0,%1,%2,%3};"
        : "+f"(d[0]), "+f"(d[1]), "+f"(d[2]), "+f"(d[3])
        : "r"(a[0]), "r"(a[1]), "r"(a[2]), "r"(a[3]), "r"(b[0]), "r"(b[1]));
}

__device__ __forceinline__ void split4(float4 v, uint2& hi, uint2& lo) {
    __nv_bfloat16 hx = __float2bfloat16(v.x);
    __nv_bfloat16 hy = __float2bfloat16(v.y);
    __nv_bfloat16 hz = __float2bfloat16(v.z);
    __nv_bfloat16 hw = __float2bfloat16(v.w);
    union { __nv_bfloat162 b[2]; uint2 u; } c;
    c.b[0] = __halves2bfloat162(hx, hy);
    c.b[1] = __halves2bfloat162(hz, hw);
    hi = c.u;
    c.b[0] = __halves2bfloat162(__float2bfloat16(v.x - __bfloat162float(hx)),
                                __float2bfloat16(v.y - __bfloat162float(hy)));
    c.b[1] = __halves2bfloat162(__float2bfloat16(v.z - __bfloat162float(hz)),
                                __float2bfloat16(v.w - __bfloat162float(hw)));
    lo = c.u;
}

// ---------------- elementwise split: fp32 -> bf16 hi/lo ----------------
__global__ __launch_bounds__(256) void split_kernel(
    const float* __restrict__ src, __nv_bfloat16* __restrict__ hi,
    __nv_bfloat16* __restrict__ lo, int n4)
{
    int i = blockIdx.x * blockDim.x + threadIdx.x;
    if (i >= n4) return;
    float4 v = ((const float4*)src)[i];
    uint2 h, l;
    split4(v, h, l);
    ((uint2*)hi)[i] = h;
    ((uint2*)lo)[i] = l;
}

// ---------------- RMSNorm (fused hi/lo split output) ----------------
__global__ __launch_bounds__(128) void rmsnorm_kernel(
    const float* __restrict__ x, const float* __restrict__ w,
    __nv_bfloat16* __restrict__ hi, __nv_bfloat16* __restrict__ lo)
{
    int row = blockIdx.x;
    const float4* xr = (const float4*)(x + (size_t)row * D_);
    const float4* wr = (const float4*)w;
    int tid = threadIdx.x;

    float4 v = xr[tid];
    float s = v.x * v.x + v.y * v.y + v.z * v.z + v.w * v.w;
    #pragma unroll
    for (int o = 16; o > 0; o >>= 1) s += __shfl_xor_sync(0xffffffffu, s, o);
    __shared__ float red[4];
    int warp = tid >> 5, lane = tid & 31;
    if (lane == 0) red[warp] = s;
    __syncthreads();
    float total = red[0] + red[1] + red[2] + red[3];
    float inv = rsqrtf(total / (float)D_ + EPS_);
    float4 wv = wr[tid];
    float4 o4 = make_float4(v.x * inv * wv.x, v.y * inv * wv.y,
                            v.z * inv * wv.z, v.w * inv * wv.w);
    uint2 h, l;
    split4(o4, h, l);
    int idx = row * (D_ / 4) + tid;
    ((uint2*)hi)[idx] = h;
    ((uint2*)lo)[idx] = l;
}

// ---------------- split-bf16 mma.sync GEMM ----------------
// C[M,N] = Ahi@Bhi + Ahi@Blo + Alo@Bhi  (+bias) (+C if accum), f32 accum.
// CTA tile 128x128, K-chunk 32 (bf16), 256 threads = 8 warps (4x2 of 32x64).
#define BKF  32
#define ASTR 40    // bf16 elems per A smem row (80B, conflict-free ldmatrix)
#define BSTR 136   // bf16 elems per B smem row (272B, conflict-free ldmatrix)

__global__ __launch_bounds__(256) void gemm_mma(
    int M, int N, int K,
    const __nv_bfloat16* __restrict__ Ahi, const __nv_bfloat16* __restrict__ Alo,
    const __nv_bfloat16* __restrict__ Bhi, const __nv_bfloat16* __restrict__ Blo,
    const float* __restrict__ bias, float* __restrict__ C, int accum)
{
    __shared__ __nv_bfloat16 As[2][128 * ASTR];
    __shared__ __nv_bfloat16 Bs[2][BKF * BSTR];

    const int tid = threadIdx.x;
    const int wid = tid >> 5, lane = tid & 31;
    const int mBase = blockIdx.y * 128;
    const int nBase = blockIdx.x * 128;
    const int warpM = (wid >> 1) * 32;   // 0,32,64,96
    const int warpN = (wid & 1) * 64;    // 0,64

    const uint32_t sA0 = smem_to_u32(As[0]);
    const uint32_t sB0 = smem_to_u32(Bs[0]);
    const uint32_t aStageB = 128 * ASTR * 2;
    const uint32_t bStageB = BKF * BSTR * 2;

    const int cpk = K / BKF;
    const int total = 3 * cpk;

    // A load: 512 x 16B segs (row=e>>2, seg=e&3); B: 512 x 16B (row=e>>4, seg=e&15)
    const int arow0 = tid >> 2, aseg = (tid & 3) * 8;
    const int brow0 = tid >> 4, bseg = (tid & 15) * 8;

    float acc[2][8][4];
    #pragma unroll
    for (int mi = 0; mi < 2; mi++)
        #pragma unroll
        for (int ni = 0; ni < 8; ni++)
            #pragma unroll
            for (int c = 0; c < 4; c++) acc[mi][ni][c] = 0.0f;

    // chunk -> (term, k0) and issue cp.asyncs
    auto issue = [&](int chunk, int buf) {
        int term = chunk / cpk;
        int k0 = (chunk - term * cpk) * BKF;
        const __nv_bfloat16* Asrc = (term < 2) ? Ahi : Alo;
        const __nv_bfloat16* Bsrc = (term == 1) ? Blo : Bhi;
        uint32_t da = sA0 + buf * aStageB;
        uint32_t db = sB0 + buf * bStageB;
        const __nv_bfloat16* aptr = Asrc + (size_t)mBase * K + k0 + aseg;
        const __nv_bfloat16* bptr = Bsrc + (size_t)k0 * N + nBase + bseg;
        #pragma unroll
        for (int it = 0; it < 2; it++) {
            int row = arow0 + it * 64;
            CP_ASYNC16(da + row * (ASTR * 2) + aseg * 2, aptr + (size_t)row * K);
        }
        #pragma unroll
        for (int it = 0; it < 2; it++) {
            int row = brow0 + it * 16;
            CP_ASYNC16(db + row * (BSTR * 2) + bseg * 2, bptr + (size_t)row * N);
        }
        CP_COMMIT();
    };

    issue(0, 0);

    for (int i = 0; i < total; i++) {
        if (i + 1 < total) { issue(i + 1, (i + 1) & 1); CP_WAIT1(); }
        else               { CP_WAIT0(); }
        __syncthreads();

        const int buf = i & 1;
        const uint32_t aBase = sA0 + buf * aStageB;
        const uint32_t bBase = sB0 + buf * bStageB;

        #pragma unroll
        for (int kk = 0; kk < 2; kk++) {
            uint32_t afrag[2][4];
            #pragma unroll
            for (int mi = 0; mi < 2; mi++) {
                uint32_t addr = aBase
                    + (warpM + mi * 16 + (lane & 15)) * (ASTR * 2)
                    + ((lane >> 4) << 4) + kk * 32;
                ldmA(afrag[mi], addr);
            }
            uint32_t bfrag[4][4];
            #pragma unroll
            for (int p = 0; p < 4; p++) {
                int grp = lane >> 3, r = lane & 7;
                uint32_t addr = bBase
                    + (kk * 16 + (grp & 1) * 8 + r) * (BSTR * 2)
                    + (warpN + p * 16 + (grp >> 1) * 8) * 2;
                ldmBT(bfrag[p], addr);
            }
            #pragma unroll
            for (int mi = 0; mi < 2; mi++)
                #pragma unroll
                for (int ni = 0; ni < 8; ni++)
                    mma16816(acc[mi][ni], afrag[mi], &bfrag[ni >> 1][(ni & 1) * 2]);
        }
        __syncthreads();
    }

    // epilogue: direct float2 stores
    #pragma unroll
    for (int mi = 0; mi < 2; mi++) {
        #pragma unroll
        for (int ni = 0; ni < 8; ni++) {
            int r0 = mBase + warpM + mi * 16 + (lane >> 2);
            int c  = nBase + warpN + ni * 8 + (lane & 3) * 2;
            float2 v0 = make_float2(acc[mi][ni][0], acc[mi][ni][1]);
            float2 v1 = make_float2(acc[mi][ni][2], acc[mi][ni][3]);
            if (bias) {
                float2 bb = *(const float2*)(bias + c);
                v0.x += bb.x; v0.y += bb.y;
                v1.x += bb.x; v1.y += bb.y;
            }
            float* p0 = C + (size_t)r0 * N + c;
            float* p1 = C + (size_t)(r0 + 8) * N + c;
            if (accum) {
                float2 c0 = *(float2*)p0, c1 = *(float2*)p1;
                v0.x += c0.x; v0.y += c0.y;
                v1.x += c1.x; v1.y += c1.y;
            }
            *(float2*)p0 = v0;
            *(float2*)p1 = v1;
        }
    }
}

// ---------------- RoPE helpers ----------------
__device__ __forceinline__ float inv_freq_f(int d)
{
    return (float)pow(10000.0, -(double)d / 32.0);
}

__global__ __launch_bounds__(256) void rope_q_kernel(
    const float* __restrict__ qp, float* __restrict__ q)
{
    int idx = blockIdx.x * blockDim.x + threadIdx.x;
    int d  = idx & 31;
    int h  = (idx >> 5) & 15;
    int qi = (idx >> 9) & 1023;
    int b  = idx >> 19;
    const float* src = qp + ((size_t)(b * LQ_ + qi) * (H_ * DQK_)) + h * DQK_;
    float x1 = src[d], x2 = src[d + 32];
    float pos = (float)(qi * BPL_);
    float ang = pos * inv_freq_f(d);
    float c = cosf(ang), s = sinf(ang);
    float* dst = q + (((size_t)(b * H_ + h) * LQ_) + qi) * DQK_;
    dst[d]      = x1 * c - x2 * s;
    dst[d + 32] = x1 * s + x2 * c;
}

__global__ __launch_bounds__(256) void rope_k_kernel(
    const float* __restrict__ kvp, float* __restrict__ k)
{
    int idx = blockIdx.x * blockDim.x + threadIdx.x;
    int d  = idx & 31;
    int h  = (idx >> 5) & 15;
    int s  = (idx >> 9) & 4095;
    int b  = idx >> 21;
    const float* src = kvp + ((size_t)(b * S_ + s) * (2 * H_ * DQK_)) + h * DQK_;
    float x1 = src[d], x2 = src[d + 32];
    float pos = (float)s;
    float ang = pos * inv_freq_f(d);
    float c = cosf(ang), sn = sinf(ang);
    float* dst = k + (((size_t)(b * H_ + h) * S_) + s) * DQK_;
    dst[d]      = x1 * c - x2 * sn;
    dst[d + 32] = x1 * sn + x2 * c;
}

__global__ __launch_bounds__(256) void vtrans_kernel(
    const float* __restrict__ kvp, float* __restrict__ v)
{
    int idx = blockIdx.x * blockDim.x + threadIdx.x;
    int d4 = idx & 15;
    int h  = (idx >> 4) & 15;
    int s  = (idx >> 8) & 4095;
    int b  = idx >> 20;
    const float4* src = (const float4*)(kvp + ((size_t)(b * S_ + s) * (2 * H_ * DQK_))
                                        + H_ * DQK_ + h * DQK_);
    float4* dst = (float4*)(v + (((size_t)(b * H_ + h) * S_) + s) * DQK_);
    dst[d4] = src[d4];
}

// ---------------- flash attention (fp32, thread-per-query) ----------------
#define FKT 32
__global__ __launch_bounds__(128) void flash_kernel(
    const float* __restrict__ q, const float* __restrict__ k,
    const float* __restrict__ v, float* __restrict__ out)
{
    const int bh = blockIdx.y;
    const int qi = blockIdx.x * 128 + threadIdx.x;

    const float* qrow = q + ((size_t)bh * LQ_ + qi) * DQK_;
    float qreg[DQK_];
    #pragma unroll
    for (int i = 0; i < 16; i++) {
        float4 t = ((const float4*)qrow)[i];
        qreg[4 * i] = t.x; qreg[4 * i + 1] = t.y; qreg[4 * i + 2] = t.z; qreg[4 * i + 3] = t.w;
    }

    __shared__ float ksm[FKT * DQK_];
    __shared__ float vsm[FKT * DQK_];
    const float* kbase = k + (size_t)bh * S_ * DQK_;
    const float* vbase = v + (size_t)bh * S_ * DQK_;

    float m = -1e30f, l = 0.0f;
    float acc[DQK_];
    #pragma unroll
    for (int d = 0; d < DQK_; d++) acc[d] = 0.0f;
    const float scale = 0.125f;

    for (int j0 = 0; j0 < S_; j0 += FKT) {
        __syncthreads();
        const float4* ksrc = (const float4*)(kbase + (size_t)j0 * DQK_);
        const float4* vsrc = (const float4*)(vbase + (size_t)j0 * DQK_);
        #pragma unroll
        for (int t = 0; t < 4; t++) {
            int i = threadIdx.x + t * 128;
            ((float4*)ksm)[i] = ksrc[i];
            ((float4*)vsm)[i] = vsrc[i];
        }
        __syncthreads();

        float sreg[FKT];
        #pragma unroll
        for (int j = 0; j < FKT; j++) {
            const float4* kr = (const float4*)&ksm[j * DQK_];
            float s = 0.0f;
            #pragma unroll
            for (int d4 = 0; d4 < 16; d4++) {
                float4 kk = kr[d4];
                s += qreg[4 * d4]     * kk.x;
                s += qreg[4 * d4 + 1] * kk.y;
                s += qreg[4 * d4 + 2] * kk.z;
                s += qreg[4 * d4 + 3] * kk.w;
            }
            sreg[j] = s * scale;
        }

        float tmax = sreg[0];
        #pragma unroll
        for (int j = 1; j < FKT; j++) tmax = fmaxf(tmax, sreg[j]);
        float mnew = fmaxf(m, tmax);
        float corr = __expf(m - mnew);
        l *= corr;
        #pragma unroll
        for (int d = 0; d < DQK_; d++) acc[d] *= corr;
        m = mnew;

        #pragma unroll
        for (int j = 0; j < FKT; j++) {
            float p = __expf(sreg[j] - m);
            l += p;
            const float4* vr = (const float4*)&vsm[j * DQK_];
            #pragma unroll
            for (int d4 = 0; d4 < 16; d4++) {
                float4 vv = vr[d4];
                acc[4 * d4]     += p * vv.x;
                acc[4 * d4 + 1] += p * vv.y;
                acc[4 * d4 + 2] += p * vv.z;
                acc[4 * d4 + 3] += p * vv.w;
            }
        }
    }

    float inv = 1.0f / l;
    int b = bh >> 4, h = bh & 15;
    float* o = out + ((size_t)(b * LQ_ + qi) * (H_ * DQK_)) + h * DQK_;
    #pragma unroll
    for (int d4 = 0; d4 < 16; d4++) {
        float4 r = make_float4(acc[4 * d4] * inv, acc[4 * d4 + 1] * inv,
                               acc[4 * d4 + 2] * inv, acc[4 * d4 + 3] * inv);
        ((float4*)o)[d4] = r;
    }
}

// ---------------- launch ----------------
extern "C" void kernel_launch(void* const* d_in, const int* in_sizes, int n_in,
                              void* d_out, int out_size)
{
    (void)in_sizes; (void)n_in; (void)out_size;
    const float* x      = (const float*)d_in[0];
    const float* norm_w = (const float*)d_in[1];
    const float* wq_w   = (const float*)d_in[2];
    const float* wq_b   = (const float*)d_in[3];
    const float* wkv_w  = (const float*)d_in[4];
    const float* wkv_b  = (const float*)d_in[5];
    const float* wout_w = (const float*)d_in[6];
    const float* wout_b = (const float*)d_in[7];
    const float* wbyp_w = (const float*)d_in[8];
    float* out = (float*)d_out;

    float *p_qproj, *p_kvproj, *p_q, *p_k, *p_v, *p_attn;
    cudaGetSymbolAddress((void**)&p_qproj,  g_qproj);
    cudaGetSymbolAddress((void**)&p_kvproj, g_kvproj);
    cudaGetSymbolAddress((void**)&p_q,      g_q);
    cudaGetSymbolAddress((void**)&p_k,      g_k);
    cudaGetSymbolAddress((void**)&p_v,      g_v);
    cudaGetSymbolAddress((void**)&p_attn,   g_attn);

    __nv_bfloat16 *nh, *nl, *xh, *xl, *wqh, *wql, *wkvh, *wkvl, *wouth, *woutl,
                  *wbyph, *wbypl, *ath, *atl;
    cudaGetSymbolAddress((void**)&nh,    g_normh);
    cudaGetSymbolAddress((void**)&nl,    g_norml);
    cudaGetSymbolAddress((void**)&xh,    g_xh);
    cudaGetSymbolAddress((void**)&xl,    g_xl);
    cudaGetSymbolAddress((void**)&wqh,   g_wqh);
    cudaGetSymbolAddress((void**)&wql,   g_wql);
    cudaGetSymbolAddress((void**)&wkvh,  g_wkvh);
    cudaGetSymbolAddress((void**)&wkvl,  g_wkvl);
    cudaGetSymbolAddress((void**)&wouth, g_wouth);
    cudaGetSymbolAddress((void**)&woutl, g_woutl);
    cudaGetSymbolAddress((void**)&wbyph, g_wbyph);
    cudaGetSymbolAddress((void**)&wbypl, g_wbypl);
    cudaGetSymbolAddress((void**)&ath,   g_attnh);
    cudaGetSymbolAddress((void**)&atl,   g_attnl);

    // 1. RMSNorm with fused hi/lo split
    rmsnorm_kernel<<<B_ * S_, 128>>>(x, norm_w, nh, nl);

    // 2. operand splits
    split_kernel<<<(B_ * S_ * D_ / 4) / 256, 256>>>(x, xh, xl, B_ * S_ * D_ / 4);
    split_kernel<<<(BPL_ * D_ * H_ * DQK_ / 4) / 256, 256>>>(wq_w, wqh, wql, BPL_ * D_ * H_ * DQK_ / 4);
    split_kernel<<<(D_ * 2 * H_ * DQK_ / 4) / 256, 256>>>(wkv_w, wkvh, wkvl, D_ * 2 * H_ * DQK_ / 4);
    split_kernel<<<(H_ * DQK_ * DLAT_ / 4) / 256, 256>>>(wout_w, wouth, woutl, H_ * DQK_ * DLAT_ / 4);
    split_kernel<<<(BPL_ * D_ * DLAT_ / 4) / 256, 256>>>(wbyp_w, wbyph, wbypl, BPL_ * D_ * DLAT_ / 4);

    // 3. Q projection: (2048 x 2048) @ (2048 x 1024) + bias
    gemm_mma<<<dim3((H_ * DQK_) / 128, (B_ * LQ_) / 128), 256>>>(
        B_ * LQ_, H_ * DQK_, BPL_ * D_, nh, nl, wqh, wql, wq_b, p_qproj, 0);

    // 4. KV projection: (8192 x 512) @ (512 x 2048) + bias
    gemm_mma<<<dim3((2 * H_ * DQK_) / 128, (B_ * S_) / 128), 256>>>(
        B_ * S_, 2 * H_ * DQK_, D_, nh, nl, wkvh, wkvl, wkv_b, p_kvproj, 0);

    // 5. RoPE + transposes
    rope_q_kernel<<<(B_ * LQ_ * H_ * 32) / 256, 256>>>(p_qproj, p_q);
    rope_k_kernel<<<(B_ * S_ * H_ * 32) / 256, 256>>>(p_kvproj, p_k);
    vtrans_kernel<<<(B_ * S_ * H_ * 16) / 256, 256>>>(p_kvproj, p_v);

    // 6. Flash attention
    flash_kernel<<<dim3(LQ_ / 128, B_ * H_), 128>>>(p_q, p_k, p_v, p_attn);

    // 7. split attention output for out-projection
    split_kernel<<<(B_ * LQ_ * H_ * DQK_ / 4) / 256, 256>>>(p_attn, ath, atl, B_ * LQ_ * H_ * DQK_ / 4);

    // 8. Bypass GEMM: out = x (2048 x 2048) @ wbyp (2048 x 1024)
    gemm_mma<<<dim3(DLAT_ / 128, (B_ * LQ_) / 128), 256>>>(
        B_ * LQ_, DLAT_, BPL_ * D_, xh, xl, wbyph, wbypl, nullptr, out, 0);

    // 9. Out projection (accumulate): out += attn @ wout + wout_b
    gemm_mma<<<dim3(DLAT_ / 128, (B_ * LQ_) / 128), 256>>>(
        B_ * LQ_, DLAT_, H_ * DQK_, ath, atl, wouth, woutl, wout_b, out, 1);
}

// round 5
// speedup vs baseline: 2.8518x; 1.9369x over previous
#include <cuda_runtime.h>
#include <cuda_bf16.h>
#include <math.h>
#include <stdint.h>

// ---------------- problem constants ----------------
#define B_   2
#define S_   4096
#define D_   512
#define BPL_ 4
#define H_   16
#define DQK_ 64
#define DLAT_ 1024
#define LQ_  (S_ / BPL_)          // 1024
#define EPS_ 1.1920929e-07f

// ---------------- scratch (device globals; no allocation allowed) ----------------
__device__ float g_qproj [B_ * LQ_ * H_ * DQK_];
__device__ float g_kvproj[B_ * S_ * 2 * H_ * DQK_];

// bf16 hi/lo split operands
__device__ __nv_bfloat16 g_normh[B_ * S_ * D_], g_norml[B_ * S_ * D_];
__device__ __nv_bfloat16 g_xh   [B_ * S_ * D_], g_xl   [B_ * S_ * D_];
__device__ __nv_bfloat16 g_wqh  [BPL_ * D_ * H_ * DQK_],  g_wql  [BPL_ * D_ * H_ * DQK_];
__device__ __nv_bfloat16 g_wkvh [D_ * 2 * H_ * DQK_],     g_wkvl [D_ * 2 * H_ * DQK_];
__device__ __nv_bfloat16 g_wouth[H_ * DQK_ * DLAT_],      g_woutl[H_ * DQK_ * DLAT_];
__device__ __nv_bfloat16 g_wbyph[BPL_ * D_ * DLAT_],      g_wbypl[BPL_ * D_ * DLAT_];
__device__ __nv_bfloat16 g_attnh[B_ * LQ_ * H_ * DQK_],   g_attnl[B_ * LQ_ * H_ * DQK_];

// bf16 hi/lo q,k,v for mma flash
__device__ __nv_bfloat16 g_qh[B_ * H_ * LQ_ * DQK_], g_ql[B_ * H_ * LQ_ * DQK_];
__device__ __nv_bfloat16 g_kh[B_ * H_ * S_ * DQK_],  g_kl[B_ * H_ * S_ * DQK_];
__device__ __nv_bfloat16 g_vh[B_ * H_ * S_ * DQK_],  g_vl[B_ * H_ * S_ * DQK_];

// ---------------- helpers ----------------
__device__ __forceinline__ uint32_t smem_to_u32(const void* p) {
    uint32_t a;
    asm("{ .reg .u64 t; cvta.to.shared.u64 t, %1; cvt.u32.u64 %0, t; }" : "=r"(a) : "l"(p));
    return a;
}

#define CP_ASYNC16(dst, src) \
    asm volatile("cp.async.cg.shared.global [%0], [%1], 16;" :: "r"(dst), "l"(src))
#define CP_COMMIT()  asm volatile("cp.async.commit_group;" ::: "memory")
#define CP_WAIT1()   asm volatile("cp.async.wait_group 1;" ::: "memory")
#define CP_WAIT0()   asm volatile("cp.async.wait_group 0;" ::: "memory")

__device__ __forceinline__ void ldmA(uint32_t* r, uint32_t addr) {
    asm volatile("ldmatrix.sync.aligned.m8n8.x4.shared.b16 {%0,%1,%2,%3}, [%4];"
                 : "=r"(r[0]), "=r"(r[1]), "=r"(r[2]), "=r"(r[3]) : "r"(addr));
}
__device__ __forceinline__ void ldmBT(uint32_t* r, uint32_t addr) {
    asm volatile("ldmatrix.sync.aligned.m8n8.x4.trans.shared.b16 {%0,%1,%2,%3}, [%4];"
                 : "=r"(r[0]), "=r"(r[1]), "=r"(r[2]), "=r"(r[3]) : "r"(addr));
}
__device__ __forceinline__ void mma16816(float* d, const uint32_t* a, const uint32_t* b) {
    asm volatile(
        "mma.sync.aligned.m16n8k16.row.col.f32.bf16.bf16.f32 "
        "{%0,%1,%2,%3}, {%4,%5,%6,%7}, {%8,%9}, {%0,%1,%2,%3};"
        : "+f"(d[0]), "+f"(d[1]), "+f"(d[2]), "+f"(d[3])
        : "r"(a[0]), "r"(a[1]), "r"(a[2]), "r"(a[3]), "r"(b[0]), "r"(b[1]));
}
__device__ __forceinline__ void mma2(float* d, const uint32_t* a, uint32_t b0, uint32_t b1) {
    asm volatile(
        "mma.sync.aligned.m16n8k16.row.col.f32.bf16.bf16.f32 "
        "{%0,%1,%2,%3}, {%4,%5,%6,%7}, {%8,%9}, {%0,%1,%2,%3};"
        : "+f"(d[0]), "+f"(d[1]), "+f"(d[2]), "+f"(d[3])
        : "r"(a[0]), "r"(a[1]), "r"(a[2]), "r"(a[3]), "r"(b0), "r"(b1));
}

__device__ __forceinline__ uint32_t packbf(float x, float y) {
    union { __nv_bfloat162 b; uint32_t u; } c;
    c.b = __halves2bfloat162(__float2bfloat16(x), __float2bfloat16(y));
    return c.u;
}

__device__ __forceinline__ void split4(float4 v, uint2& hi, uint2& lo) {
    __nv_bfloat16 hx = __float2bfloat16(v.x);
    __nv_bfloat16 hy = __float2bfloat16(v.y);
    __nv_bfloat16 hz = __float2bfloat16(v.z);
    __nv_bfloat16 hw = __float2bfloat16(v.w);
    union { __nv_bfloat162 b[2]; uint2 u; } c;
    c.b[0] = __halves2bfloat162(hx, hy);
    c.b[1] = __halves2bfloat162(hz, hw);
    hi = c.u;
    c.b[0] = __halves2bfloat162(__float2bfloat16(v.x - __bfloat162float(hx)),
                                __float2bfloat16(v.y - __bfloat162float(hy)));
    c.b[1] = __halves2bfloat162(__float2bfloat16(v.z - __bfloat162float(hz)),
                                __float2bfloat16(v.w - __bfloat162float(hw)));
    lo = c.u;
}

// ---------------- elementwise split: fp32 -> bf16 hi/lo ----------------
__global__ __launch_bounds__(256) void split_kernel(
    const float* __restrict__ src, __nv_bfloat16* __restrict__ hi,
    __nv_bfloat16* __restrict__ lo, int n4)
{
    int i = blockIdx.x * blockDim.x + threadIdx.x;
    if (i >= n4) return;
    float4 v = ((const float4*)src)[i];
    uint2 h, l;
    split4(v, h, l);
    ((uint2*)hi)[i] = h;
    ((uint2*)lo)[i] = l;
}

// ---------------- RMSNorm (fused hi/lo split output) ----------------
__global__ __launch_bounds__(128) void rmsnorm_kernel(
    const float* __restrict__ x, const float* __restrict__ w,
    __nv_bfloat16* __restrict__ hi, __nv_bfloat16* __restrict__ lo)
{
    int row = blockIdx.x;
    const float4* xr = (const float4*)(x + (size_t)row * D_);
    const float4* wr = (const float4*)w;
    int tid = threadIdx.x;

    float4 v = xr[tid];
    float s = v.x * v.x + v.y * v.y + v.z * v.z + v.w * v.w;
    #pragma unroll
    for (int o = 16; o > 0; o >>= 1) s += __shfl_xor_sync(0xffffffffu, s, o);
    __shared__ float red[4];
    int warp = tid >> 5, lane = tid & 31;
    if (lane == 0) red[warp] = s;
    __syncthreads();
    float total = red[0] + red[1] + red[2] + red[3];
    float inv = rsqrtf(total / (float)D_ + EPS_);
    float4 wv = wr[tid];
    float4 o4 = make_float4(v.x * inv * wv.x, v.y * inv * wv.y,
                            v.z * inv * wv.z, v.w * inv * wv.w);
    uint2 h, l;
    split4(o4, h, l);
    int idx = row * (D_ / 4) + tid;
    ((uint2*)hi)[idx] = h;
    ((uint2*)lo)[idx] = l;
}

// ---------------- split-bf16 mma.sync GEMM ----------------
#define BKF  32
#define ASTR 40
#define BSTR 136

__global__ __launch_bounds__(256) void gemm_mma(
    int M, int N, int K,
    const __nv_bfloat16* __restrict__ Ahi, const __nv_bfloat16* __restrict__ Alo,
    const __nv_bfloat16* __restrict__ Bhi, const __nv_bfloat16* __restrict__ Blo,
    const float* __restrict__ bias, float* __restrict__ C, int accum)
{
    __shared__ __nv_bfloat16 As[2][128 * ASTR];
    __shared__ __nv_bfloat16 Bs[2][BKF * BSTR];

    const int tid = threadIdx.x;
    const int wid = tid >> 5, lane = tid & 31;
    const int mBase = blockIdx.y * 128;
    const int nBase = blockIdx.x * 128;
    const int warpM = (wid >> 1) * 32;
    const int warpN = (wid & 1) * 64;

    const uint32_t sA0 = smem_to_u32(As[0]);
    const uint32_t sB0 = smem_to_u32(Bs[0]);
    const uint32_t aStageB = 128 * ASTR * 2;
    const uint32_t bStageB = BKF * BSTR * 2;

    const int cpk = K / BKF;
    const int total = 3 * cpk;

    const int arow0 = tid >> 2, aseg = (tid & 3) * 8;
    const int brow0 = tid >> 4, bseg = (tid & 15) * 8;

    float acc[2][8][4];
    #pragma unroll
    for (int mi = 0; mi < 2; mi++)
        #pragma unroll
        for (int ni = 0; ni < 8; ni++)
            #pragma unroll
            for (int c = 0; c < 4; c++) acc[mi][ni][c] = 0.0f;

    auto issue = [&](int chunk, int buf) {
        int term = chunk / cpk;
        int k0 = (chunk - term * cpk) * BKF;
        const __nv_bfloat16* Asrc = (term < 2) ? Ahi : Alo;
        const __nv_bfloat16* Bsrc = (term == 1) ? Blo : Bhi;
        uint32_t da = sA0 + buf * aStageB;
        uint32_t db = sB0 + buf * bStageB;
        const __nv_bfloat16* aptr = Asrc + (size_t)mBase * K + k0 + aseg;
        const __nv_bfloat16* bptr = Bsrc + (size_t)k0 * N + nBase + bseg;
        #pragma unroll
        for (int it = 0; it < 2; it++) {
            int row = arow0 + it * 64;
            CP_ASYNC16(da + row * (ASTR * 2) + aseg * 2, aptr + (size_t)row * K);
        }
        #pragma unroll
        for (int it = 0; it < 2; it++) {
            int row = brow0 + it * 16;
            CP_ASYNC16(db + row * (BSTR * 2) + bseg * 2, bptr + (size_t)row * N);
        }
        CP_COMMIT();
    };

    issue(0, 0);

    for (int i = 0; i < total; i++) {
        if (i + 1 < total) { issue(i + 1, (i + 1) & 1); CP_WAIT1(); }
        else               { CP_WAIT0(); }
        __syncthreads();

        const int buf = i & 1;
        const uint32_t aBase = sA0 + buf * aStageB;
        const uint32_t bBase = sB0 + buf * bStageB;

        #pragma unroll
        for (int kk = 0; kk < 2; kk++) {
            uint32_t afrag[2][4];
            #pragma unroll
            for (int mi = 0; mi < 2; mi++) {
                uint32_t addr = aBase
                    + (warpM + mi * 16 + (lane & 15)) * (ASTR * 2)
                    + ((lane >> 4) << 4) + kk * 32;
                ldmA(afrag[mi], addr);
            }
            uint32_t bfrag[4][4];
            #pragma unroll
            for (int p = 0; p < 4; p++) {
                int grp = lane >> 3, r = lane & 7;
                uint32_t addr = bBase
                    + (kk * 16 + (grp & 1) * 8 + r) * (BSTR * 2)
                    + (warpN + p * 16 + (grp >> 1) * 8) * 2;
                ldmBT(bfrag[p], addr);
            }
            #pragma unroll
            for (int mi = 0; mi < 2; mi++)
                #pragma unroll
                for (int ni = 0; ni < 8; ni++)
                    mma16816(acc[mi][ni], afrag[mi], &bfrag[ni >> 1][(ni & 1) * 2]);
        }
        __syncthreads();
    }

    #pragma unroll
    for (int mi = 0; mi < 2; mi++) {
        #pragma unroll
        for (int ni = 0; ni < 8; ni++) {
            int r0 = mBase + warpM + mi * 16 + (lane >> 2);
            int c  = nBase + warpN + ni * 8 + (lane & 3) * 2;
            float2 v0 = make_float2(acc[mi][ni][0], acc[mi][ni][1]);
            float2 v1 = make_float2(acc[mi][ni][2], acc[mi][ni][3]);
            if (bias) {
                float2 bb = *(const float2*)(bias + c);
                v0.x += bb.x; v0.y += bb.y;
                v1.x += bb.x; v1.y += bb.y;
            }
            float* p0 = C + (size_t)r0 * N + c;
            float* p1 = C + (size_t)(r0 + 8) * N + c;
            if (accum) {
                float2 c0 = *(float2*)p0, c1 = *(float2*)p1;
                v0.x += c0.x; v0.y += c0.y;
                v1.x += c1.x; v1.y += c1.y;
            }
            *(float2*)p0 = v0;
            *(float2*)p1 = v1;
        }
    }
}

// ---------------- RoPE: emit bf16 hi/lo directly ----------------
__device__ __forceinline__ float inv_freq_f(int d)
{
    return (float)pow(10000.0, -(double)d / 32.0);
}

__device__ __forceinline__ void store_hl(__nv_bfloat16* hi, __nv_bfloat16* lo,
                                         size_t idx, float v)
{
    __nv_bfloat16 h = __float2bfloat16(v);
    hi[idx] = h;
    lo[idx] = __float2bfloat16(v - __bfloat162float(h));
}

// q: (B,LQ,H,64) fp32 -> rope -> *0.125 (exact pow2) -> (B,H,LQ,64) bf16 hi/lo
__global__ __launch_bounds__(256) void rope_q_kernel(
    const float* __restrict__ qp,
    __nv_bfloat16* __restrict__ qhi, __nv_bfloat16* __restrict__ qlo)
{
    int idx = blockIdx.x * blockDim.x + threadIdx.x;
    int d  = idx & 31;
    int h  = (idx >> 5) & 15;
    int qi = (idx >> 9) & 1023;
    int b  = idx >> 19;
    const float* src = qp + ((size_t)(b * LQ_ + qi) * (H_ * DQK_)) + h * DQK_;
    float x1 = src[d], x2 = src[d + 32];
    float pos = (float)(qi * BPL_);
    float ang = pos * inv_freq_f(d);
    float c = cosf(ang), s = sinf(ang);
    size_t base = (((size_t)(b * H_ + h) * LQ_) + qi) * DQK_;
    store_hl(qhi, qlo, base + d,      (x1 * c - x2 * s) * 0.125f);
    store_hl(qhi, qlo, base + d + 32, (x1 * s + x2 * c) * 0.125f);
}

__global__ __launch_bounds__(256) void rope_k_kernel(
    const float* __restrict__ kvp,
    __nv_bfloat16* __restrict__ khi, __nv_bfloat16* __restrict__ klo)
{
    int idx = blockIdx.x * blockDim.x + threadIdx.x;
    int d  = idx & 31;
    int h  = (idx >> 5) & 15;
    int s  = (idx >> 9) & 4095;
    int b  = idx >> 21;
    const float* src = kvp + ((size_t)(b * S_ + s) * (2 * H_ * DQK_)) + h * DQK_;
    float x1 = src[d], x2 = src[d + 32];
    float pos = (float)s;
    float ang = pos * inv_freq_f(d);
    float c = cosf(ang), sn = sinf(ang);
    size_t base = (((size_t)(b * H_ + h) * S_) + s) * DQK_;
    store_hl(khi, klo, base + d,      x1 * c - x2 * sn);
    store_hl(khi, klo, base + d + 32, x1 * sn + x2 * c);
}

__global__ __launch_bounds__(256) void vtrans_kernel(
    const float* __restrict__ kvp,
    __nv_bfloat16* __restrict__ vhi, __nv_bfloat16* __restrict__ vlo)
{
    int idx = blockIdx.x * blockDim.x + threadIdx.x;
    int d4 = idx & 15;
    int h  = (idx >> 4) & 15;
    int s  = (idx >> 8) & 4095;
    int b  = idx >> 20;
    const float4* src = (const float4*)(kvp + ((size_t)(b * S_ + s) * (2 * H_ * DQK_))
                                        + H_ * DQK_ + h * DQK_);
    float4 v = src[d4];
    uint2 hi, lo;
    split4(v, hi, lo);
    size_t base = (((size_t)(b * H_ + h) * S_) + s) * DQK_;
    ((uint2*)(vhi + base))[d4] = hi;
    ((uint2*)(vlo + base))[d4] = lo;
}

// ---------------- flash attention via mma.sync (split-bf16 3-term) ----------------
// 8 warps, 128 queries/CTA (16 rows per warp), key tiles of 64, double-buffered.
// smem per stage: khi,klo,vhi,vlo each 64 rows x 144B = 9216B -> 36864B; 2 stages.
#define FSTG 36864
#define FSMEM (2 * FSTG)

__global__ __launch_bounds__(256) void flash_mma(
    const __nv_bfloat16* __restrict__ qh, const __nv_bfloat16* __restrict__ ql,
    const __nv_bfloat16* __restrict__ kh, const __nv_bfloat16* __restrict__ kl,
    const __nv_bfloat16* __restrict__ vh, const __nv_bfloat16* __restrict__ vl,
    __nv_bfloat16* __restrict__ oh, __nv_bfloat16* __restrict__ ol)
{
    extern __shared__ char sm[];
    const uint32_t sb = smem_to_u32(sm);
    const int tid = threadIdx.x, wid = tid >> 5, lane = tid & 31;
    const int bh = blockIdx.y;
    const int q0 = blockIdx.x * 128;
    const int warpM = wid * 16;
    const size_t qoff = ((size_t)bh * LQ_ + q0) * DQK_;
    const size_t koff = (size_t)bh * S_ * DQK_;

    // Q -> stage1 region (consumed before tile1 overwrites it)
    {
        #pragma unroll
        for (int it = 0; it < 4; it++) {
            int e = it * 256 + tid;
            int row = e >> 3, seg = (e & 7) * 8;
            const size_t g = qoff + (size_t)row * DQK_ + seg;
            CP_ASYNC16(sb + FSTG + row * 144 + seg * 2, qh + g);
            CP_ASYNC16(sb + FSTG + 18432 + row * 144 + seg * 2, ql + g);
        }
        CP_COMMIT();
    }

    auto issueKV = [&](int tile, int stage) {
        int sk = tile * 64;
        uint32_t dst = sb + stage * FSTG;
        #pragma unroll
        for (int it = 0; it < 2; it++) {
            int e = it * 256 + tid;
            int row = e >> 3, seg = (e & 7) * 8;
            size_t g = koff + (size_t)(sk + row) * DQK_ + seg;
            uint32_t so = row * 144 + seg * 2;
            CP_ASYNC16(dst + so,         kh + g);
            CP_ASYNC16(dst + 9216 + so,  kl + g);
            CP_ASYNC16(dst + 18432 + so, vh + g);
            CP_ASYNC16(dst + 27648 + so, vl + g);
        }
    };

    issueKV(0, 0); CP_COMMIT();
    CP_WAIT1(); __syncthreads();

    // Q fragments (16 rows x 64 k) hi/lo
    uint32_t Qh[4][4], Ql[4][4];
    #pragma unroll
    for (int kt = 0; kt < 4; kt++) {
        uint32_t ad = sb + FSTG + (warpM + (lane & 15)) * 144 + ((lane >> 4) << 4) + kt * 32;
        ldmA(Qh[kt], ad);
        ldmA(Ql[kt], ad + 18432);
    }
    __syncthreads();
    issueKV(1, 1); CP_COMMIT();

    float acc[8][4];
    #pragma unroll
    for (int n = 0; n < 8; n++)
        #pragma unroll
        for (int c = 0; c < 4; c++) acc[n][c] = 0.0f;
    float m0 = -1e30f, m1 = -1e30f, l0 = 0.0f, l1 = 0.0f;

    for (int i = 0; i < S_ / 64; i++) {
        CP_WAIT1(); __syncthreads();
        const uint32_t kb = sb + (i & 1) * FSTG;

        // scores = Qhi@Khi + Qhi@Klo + Qlo@Khi (Q pre-scaled by 0.125)
        float sc[8][4];
        #pragma unroll
        for (int n = 0; n < 8; n++)
            #pragma unroll
            for (int c = 0; c < 4; c++) sc[n][c] = 0.0f;

        #pragma unroll
        for (int kt = 0; kt < 4; kt++) {
            uint32_t Bh[4][4], Bl[4][4];
            #pragma unroll
            for (int p = 0; p < 4; p++) {
                uint32_t ad = kb + (p * 16 + (lane & 15)) * 144 + ((lane >> 4) << 4) + kt * 32;
                ldmA(Bh[p], ad);
                ldmA(Bl[p], ad + 9216);
            }
            #pragma unroll
            for (int ni = 0; ni < 8; ni++) {
                int g = ni >> 1, s = ni & 1;
                mma2(sc[ni], Qh[kt], Bh[g][s], Bh[g][s + 2]);
                mma2(sc[ni], Qh[kt], Bl[g][s], Bl[g][s + 2]);
                mma2(sc[ni], Ql[kt], Bh[g][s], Bh[g][s + 2]);
            }
        }

        // online softmax (rows: lane>>2 and +8)
        float r0 = -1e30f, r1 = -1e30f;
        #pragma unroll
        for (int ni = 0; ni < 8; ni++) {
            r0 = fmaxf(r0, fmaxf(sc[ni][0], sc[ni][1]));
            r1 = fmaxf(r1, fmaxf(sc[ni][2], sc[ni][3]));
        }
        r0 = fmaxf(r0, __shfl_xor_sync(0xffffffffu, r0, 1));
        r0 = fmaxf(r0, __shfl_xor_sync(0xffffffffu, r0, 2));
        r1 = fmaxf(r1, __shfl_xor_sync(0xffffffffu, r1, 1));
        r1 = fmaxf(r1, __shfl_xor_sync(0xffffffffu, r1, 2));
        float mn0 = fmaxf(m0, r0), mn1 = fmaxf(m1, r1);
        float c0 = __expf(m0 - mn0), c1 = __expf(m1 - mn1);
        l0 *= c0; l1 *= c1;
        #pragma unroll
        for (int ni = 0; ni < 8; ni++) {
            acc[ni][0] *= c0; acc[ni][1] *= c0;
            acc[ni][2] *= c1; acc[ni][3] *= c1;
        }
        m0 = mn0; m1 = mn1;

        // P = exp(sc - m); split hi/lo; acc += Phi@Vhi + Phi@Vlo + Plo@Vhi
        #pragma unroll
        for (int kt = 0; kt < 4; kt++) {
            uint32_t ph[4], pl[4];
            #pragma unroll
            for (int j = 0; j < 2; j++) {
                int ni = 2 * kt + j;
                float p0 = __expf(sc[ni][0] - m0);
                float p1 = __expf(sc[ni][1] - m0);
                float p2 = __expf(sc[ni][2] - m1);
                float p3 = __expf(sc[ni][3] - m1);
                l0 += p0 + p1; l1 += p2 + p3;
                float h0 = __bfloat162float(__float2bfloat16(p0));
                float h1 = __bfloat162float(__float2bfloat16(p1));
                float h2 = __bfloat162float(__float2bfloat16(p2));
                float h3 = __bfloat162float(__float2bfloat16(p3));
                ph[2 * j]     = packbf(h0, h1);
                ph[2 * j + 1] = packbf(h2, h3);
                pl[2 * j]     = packbf(p0 - h0, p1 - h1);
                pl[2 * j + 1] = packbf(p2 - h2, p3 - h3);
            }
            uint32_t Vh[4][4], Vl[4][4];
            int grp = lane >> 3, rr = lane & 7;
            #pragma unroll
            for (int p = 0; p < 4; p++) {
                uint32_t ad = kb + 18432
                    + (kt * 16 + (grp & 1) * 8 + rr) * 144
                    + (p * 16 + (grp >> 1) * 8) * 2;
                ldmBT(Vh[p], ad);
                ldmBT(Vl[p], ad + 9216);
            }
            #pragma unroll
            for (int nv = 0; nv < 8; nv++) {
                int g = nv >> 1, s = (nv & 1) * 2;
                mma2(acc[nv], ph, Vh[g][s], Vh[g][s + 1]);
                mma2(acc[nv], ph, Vl[g][s], Vl[g][s + 1]);
                mma2(acc[nv], pl, Vh[g][s], Vh[g][s + 1]);
            }
        }

        __syncthreads();
        if (i + 2 < S_ / 64) issueKV(i + 2, i & 1);
        CP_COMMIT();
    }

    // finalize: quad-reduce l, normalize, emit hi/lo bf16 attn
    l0 += __shfl_xor_sync(0xffffffffu, l0, 1);
    l0 += __shfl_xor_sync(0xffffffffu, l0, 2);
    l1 += __shfl_xor_sync(0xffffffffu, l1, 1);
    l1 += __shfl_xor_sync(0xffffffffu, l1, 2);
    float i0 = 1.0f / l0, i1 = 1.0f / l1;

    int b = bh >> 4, h = bh & 15;
    int row0 = q0 + warpM + (lane >> 2);
    size_t ob0 = (size_t)(b * LQ_ + row0) * (H_ * DQK_) + h * DQK_;
    size_t ob1 = ob0 + (size_t)8 * (H_ * DQK_);
    #pragma unroll
    for (int nv = 0; nv < 8; nv++) {
        int col = nv * 8 + (lane & 3) * 2;
        float a0 = acc[nv][0] * i0, a1 = acc[nv][1] * i0;
        float a2 = acc[nv][2] * i1, a3 = acc[nv][3] * i1;
        float h0 = __bfloat162float(__float2bfloat16(a0));
        float h1 = __bfloat162float(__float2bfloat16(a1));
        float h2 = __bfloat162float(__float2bfloat16(a2));
        float h3 = __bfloat162float(__float2bfloat16(a3));
        *(uint32_t*)(oh + ob0 + col) = packbf(a0, a1);
        *(uint32_t*)(ol + ob0 + col) = packbf(a0 - h0, a1 - h1);
        *(uint32_t*)(oh + ob1 + col) = packbf(a2, a3);
        *(uint32_t*)(ol + ob1 + col) = packbf(a2 - h2, a3 - h3);
    }
}

// ---------------- launch ----------------
extern "C" void kernel_launch(void* const* d_in, const int* in_sizes, int n_in,
                              void* d_out, int out_size)
{
    (void)in_sizes; (void)n_in; (void)out_size;
    const float* x      = (const float*)d_in[0];
    const float* norm_w = (const float*)d_in[1];
    const float* wq_w   = (const float*)d_in[2];
    const float* wq_b   = (const float*)d_in[3];
    const float* wkv_w  = (const float*)d_in[4];
    const float* wkv_b  = (const float*)d_in[5];
    const float* wout_w = (const float*)d_in[6];
    const float* wout_b = (const float*)d_in[7];
    const float* wbyp_w = (const float*)d_in[8];
    float* out = (float*)d_out;

    float *p_qproj, *p_kvproj;
    cudaGetSymbolAddress((void**)&p_qproj,  g_qproj);
    cudaGetSymbolAddress((void**)&p_kvproj, g_kvproj);

    __nv_bfloat16 *nh, *nl, *xh, *xl, *wqh, *wql, *wkvh, *wkvl, *wouth, *woutl,
                  *wbyph, *wbypl, *ath, *atl, *pqh, *pql, *pkh, *pkl, *pvh, *pvl;
    cudaGetSymbolAddress((void**)&nh,    g_normh);
    cudaGetSymbolAddress((void**)&nl,    g_norml);
    cudaGetSymbolAddress((void**)&xh,    g_xh);
    cudaGetSymbolAddress((void**)&xl,    g_xl);
    cudaGetSymbolAddress((void**)&wqh,   g_wqh);
    cudaGetSymbolAddress((void**)&wql,   g_wql);
    cudaGetSymbolAddress((void**)&wkvh,  g_wkvh);
    cudaGetSymbolAddress((void**)&wkvl,  g_wkvl);
    cudaGetSymbolAddress((void**)&wouth, g_wouth);
    cudaGetSymbolAddress((void**)&woutl, g_woutl);
    cudaGetSymbolAddress((void**)&wbyph, g_wbyph);
    cudaGetSymbolAddress((void**)&wbypl, g_wbypl);
    cudaGetSymbolAddress((void**)&ath,   g_attnh);
    cudaGetSymbolAddress((void**)&atl,   g_attnl);
    cudaGetSymbolAddress((void**)&pqh,   g_qh);
    cudaGetSymbolAddress((void**)&pql,   g_ql);
    cudaGetSymbolAddress((void**)&pkh,   g_kh);
    cudaGetSymbolAddress((void**)&pkl,   g_kl);
    cudaGetSymbolAddress((void**)&pvh,   g_vh);
    cudaGetSymbolAddress((void**)&pvl,   g_vl);

    cudaFuncSetAttribute(flash_mma, cudaFuncAttributeMaxDynamicSharedMemorySize, FSMEM);

    // 1. RMSNorm with fused hi/lo split
    rmsnorm_kernel<<<B_ * S_, 128>>>(x, norm_w, nh, nl);

    // 2. operand splits
    split_kernel<<<(B_ * S_ * D_ / 4) / 256, 256>>>(x, xh, xl, B_ * S_ * D_ / 4);
    split_kernel<<<(BPL_ * D_ * H_ * DQK_ / 4) / 256, 256>>>(wq_w, wqh, wql, BPL_ * D_ * H_ * DQK_ / 4);
    split_kernel<<<(D_ * 2 * H_ * DQK_ / 4) / 256, 256>>>(wkv_w, wkvh, wkvl, D_ * 2 * H_ * DQK_ / 4);
    split_kernel<<<(H_ * DQK_ * DLAT_ / 4) / 256, 256>>>(wout_w, wouth, woutl, H_ * DQK_ * DLAT_ / 4);
    split_kernel<<<(BPL_ * D_ * DLAT_ / 4) / 256, 256>>>(wbyp_w, wbyph, wbypl, BPL_ * D_ * DLAT_ / 4);

    // 3. Q projection
    gemm_mma<<<dim3((H_ * DQK_) / 128, (B_ * LQ_) / 128), 256>>>(
        B_ * LQ_, H_ * DQK_, BPL_ * D_, nh, nl, wqh, wql, wq_b, p_qproj, 0);

    // 4. KV projection
    gemm_mma<<<dim3((2 * H_ * DQK_) / 128, (B_ * S_) / 128), 256>>>(
        B_ * S_, 2 * H_ * DQK_, D_, nh, nl, wkvh, wkvl, wkv_b, p_kvproj, 0);

    // 5. RoPE + transposes -> bf16 hi/lo
    rope_q_kernel<<<(B_ * LQ_ * H_ * 32) / 256, 256>>>(p_qproj, pqh, pql);
    rope_k_kernel<<<(B_ * S_ * H_ * 32) / 256, 256>>>(p_kvproj, pkh, pkl);
    vtrans_kernel<<<(B_ * S_ * H_ * 16) / 256, 256>>>(p_kvproj, pvh, pvl);

    // 6. Flash attention (tensor cores) -> attn hi/lo
    flash_mma<<<dim3(LQ_ / 128, B_ * H_), 256, FSMEM>>>(
        pqh, pql, pkh, pkl, pvh, pvl, ath, atl);

    // 7. Bypass GEMM
    gemm_mma<<<dim3(DLAT_ / 128, (B_ * LQ_) / 128), 256>>>(
        B_ * LQ_, DLAT_, BPL_ * D_, xh, xl, wbyph, wbypl, nullptr, out, 0);

    // 8. Out projection (accumulate)
    gemm_mma<<<dim3(DLAT_ / 128, (B_ * LQ_) / 128), 256>>>(
        B_ * LQ_, DLAT_, H_ * DQK_, ath, atl, wouth, woutl, wout_b, out, 1);
}